// round 11
// baseline (speedup 1.0000x reference)
#include <cuda_runtime.h>
#include <cuda_bf16.h>
#include <cuda_fp16.h>
#include <cstdint>
#include <cstddef>

#define SEQ 128
#define BATCH 64
#define EMB 1024
#define HID 1024
#define OUT_DIM 32000
#define VOCAB 32000
#define RNN_BLOCKS 128

// HMMA GEMM config: 128x128 block, 4 warps of 64x64, BK=32, 4 stages
#define KE 2048                  // fp16 2-term (xh path, A side)
#define KF1 1024                 // fp16 1-term (output path)
#define BM 128
#define BN 128
#define BKK 32
#define SROW 80
#define STG_BYTES_TC ((BM + BN) * SROW)
#define STAGES_TC 4
#define SMEM_TC (STAGES_TC * STG_BYTES_TC)       // 81920

// recurrence persistent kernel config
#define K2 3072                  // bf16 3-term chunked (recurrence)
#define CH3 384
#define SUBC 12
#define SA_BYTES (SUBC * 64 * SROW)              // 61440
#define SMEM_RNN (2 * SA_BYTES)                  // 122880

// ---------------- device scratch ----------------
__device__ __align__(16) float g_xh[SEQ * BATCH * HID];               // xh + biases; phase-A reds land here
__device__ __align__(16) __half g_hallf[SEQ * BATCH * KF1];           // 16.8 MB
__device__ __align__(16) __half g_wfcf[OUT_DIM * HID];                // 64 MB
__device__ __align__(16) __half g_wihf[HID * HID];                    // 2 MB
__device__ __align__(16) __half g_embf[SEQ * BATCH * KE];             // 33.5 MB [hi|lo]
__device__ __align__(16) __nv_bfloat16 g_whh2[HID * K2];              // 6 MB [hi|lo|hi] chunked
__device__ __align__(16) __nv_bfloat16 g_h2[BATCH * K2];              // init h only
__device__ int g_idx[SEQ * BATCH];
__device__ int g_is64;
__device__ unsigned g_arrive;

// ---------------- helpers ----------------
__device__ __forceinline__ uint32_t smem_u32(const void* p) {
    uint32_t a;
    asm("{ .reg .u64 t; cvta.to.shared.u64 t, %1; cvt.u32.u64 %0, t; }" : "=r"(a) : "l"(p));
    return a;
}
__device__ __forceinline__ void cp16(uint32_t s, const void* g) {
    asm volatile("cp.async.cg.shared.global [%0], [%1], 16;" :: "r"(s), "l"(g) : "memory");
}
__device__ __forceinline__ void ldmx4(uint32_t& r0, uint32_t& r1, uint32_t& r2, uint32_t& r3, uint32_t addr) {
    asm volatile("ldmatrix.sync.aligned.m8n8.x4.shared.b16 {%0,%1,%2,%3}, [%4];"
                 : "=r"(r0), "=r"(r1), "=r"(r2), "=r"(r3) : "r"(addr));
}
__device__ __forceinline__ void mma_bf16(float* c, const uint32_t* a, const uint32_t* b) {
    asm volatile("mma.sync.aligned.m16n8k16.row.col.f32.bf16.bf16.f32 "
                 "{%0,%1,%2,%3}, {%4,%5,%6,%7}, {%8,%9}, {%0,%1,%2,%3};"
                 : "+f"(c[0]), "+f"(c[1]), "+f"(c[2]), "+f"(c[3])
                 : "r"(a[0]), "r"(a[1]), "r"(a[2]), "r"(a[3]), "r"(b[0]), "r"(b[1]));
}
__device__ __forceinline__ void mma_fp16(float* c, const uint32_t* a, const uint32_t* b) {
    asm volatile("mma.sync.aligned.m16n8k16.row.col.f32.f16.f16.f32 "
                 "{%0,%1,%2,%3}, {%4,%5,%6,%7}, {%8,%9}, {%0,%1,%2,%3};"
                 : "+f"(c[0]), "+f"(c[1]), "+f"(c[2]), "+f"(c[3])
                 : "r"(a[0]), "r"(a[1]), "r"(a[2]), "r"(a[3]), "r"(b[0]), "r"(b[1]));
}
__device__ __forceinline__ void redadd(float* p, float v) {
    asm volatile("red.relaxed.gpu.global.add.f32 [%0], %1;" :: "l"(p), "f"(v) : "memory");
}
// grid sync: release/acquire monotonic counter
__device__ __forceinline__ void gsync(unsigned target) {
    __syncthreads();
    if (threadIdx.x == 0) {
        asm volatile("red.release.gpu.global.add.u32 [%0], 1;" :: "l"(&g_arrive) : "memory");
        unsigned v;
        do {
            asm volatile("ld.acquire.gpu.global.u32 %0, [%1];" : "=r"(v) : "l"(&g_arrive) : "memory");
        } while (v < target);
    }
    __syncthreads();
}

// ---------------- small kernels ----------------
__global__ void k_sniff(const void* x) {
    __shared__ int bad;
    if (threadIdx.x == 0) bad = 0;
    __syncthreads();
    const unsigned long long* p = (const unsigned long long*)x;
    int mybad = 0;
    for (int i = threadIdx.x; i < 4096; i += 256)
        if (p[i] >= (unsigned long long)VOCAB) mybad = 1;
    if (mybad) atomicOr(&bad, 1);
    __syncthreads();
    if (threadIdx.x == 0) g_is64 = bad ? 0 : 1;
}
__global__ void k_decode(const void* x) {
    int i = blockIdx.x * 256 + threadIdx.x;
    if (i >= SEQ * BATCH) return;
    if (g_is64) g_idx[i] = (int)((const long long*)x)[i];
    else        g_idx[i] = ((const int*)x)[i];
}
// init h2 (bf16 chunked split [hi|hi|lo]) and reset grid-sync counter
__global__ void k_copyh(const float* __restrict__ hidden) {
    int i = blockIdx.x * 256 + threadIdx.x;
    if (i == 0) g_arrive = 0;
    if (i >= BATCH * HID) return;
    float v = hidden[i];
    __nv_bfloat16 hi = __float2bfloat16(v);
    __nv_bfloat16 lo = __float2bfloat16(v - __bfloat162float(hi));
    int b = i >> 10, j = i & 1023;
    int c = j >> 7, o = j & 127;
    __nv_bfloat16* hb = g_h2 + (size_t)b * K2 + c * CH3 + o;
    hb[0] = hi; hb[128] = hi; hb[256] = lo;
}
// W_hh fp32 -> bf16 chunked [hi | lo | hi] per 128-k chunk
__global__ void k_conv_whh(const float* __restrict__ W) {
    int i = blockIdx.x * 256 + threadIdx.x;
    if (i >= HID * HID) return;
    float v = W[i];
    __nv_bfloat16 hi = __float2bfloat16(v);
    __nv_bfloat16 lo = __float2bfloat16(v - __bfloat162float(hi));
    int row = i >> 10, j = i & 1023;
    int c = j >> 7, o = j & 127;
    __nv_bfloat16* b = g_whh2 + (size_t)row * K2 + c * CH3 + o;
    b[0] = hi; b[128] = lo; b[256] = hi;
}
// fp32 -> fp16 (vectorized), for W_fc and W_ih
__global__ void k_convw_f(const float* __restrict__ W, __half* __restrict__ dst, int n4) {
    int i = blockIdx.x * 256 + threadIdx.x;
    if (i >= n4) return;
    float4 v = ((const float4*)W)[i];
    __half2 a = __floats2half2_rn(v.x, v.y);
    __half2 b = __floats2half2_rn(v.z, v.w);
    ((uint2*)dst)[i] = make_uint2(*(uint32_t*)&a, *(uint32_t*)&b);
}
// gather emb rows, split to fp16 segments [hi | lo]
__global__ void k_gather_split(const float* __restrict__ emb) {
    int r = blockIdx.x;
    int t = threadIdx.x;
    long long src = g_idx[r];
    float4 v = ((const float4*)(emb + (size_t)src * 1024))[t];
    __half h0 = __float2half(v.x), h1 = __float2half(v.y);
    __half h2 = __float2half(v.z), h3 = __float2half(v.w);
    __half l0 = __float2half(v.x - __half2float(h0));
    __half l1 = __float2half(v.y - __half2float(h1));
    __half l2 = __float2half(v.z - __half2float(h2));
    __half l3 = __float2half(v.w - __half2float(h3));
    uint2 hp, lp;
    ((__half*)&hp)[0] = h0; ((__half*)&hp)[1] = h1;
    ((__half*)&hp)[2] = h2; ((__half*)&hp)[3] = h3;
    ((__half*)&lp)[0] = l0; ((__half*)&lp)[1] = l1;
    ((__half*)&lp)[2] = l2; ((__half*)&lp)[3] = l3;
    __half* base = g_embf + (size_t)r * KE;
    ((uint2*)base)[t] = hp;
    ((uint2*)(base + 1024))[t] = lp;
}

// ---------------- persistent recurrence (HMMA bf16 3-term, 1 gsync/step) ----------------
// 128 blocks (16 nx x 8 kz) x 256 thr. W slice SMEM-resident all steps.
// Phase A: 64x64 partial -> red.add into g_xh[s] (pre-initialized with xh+biases).
// gsync. Phase B: each block redundantly computes tanh for ITS h slice (batch x
// 128 k-slice kz) and writes the bf16 3-term operand straight into its SMEM A
// tile — no global h round trip, no second gsync. hallf / final out written by
// owner blocks (b%16==nx) only.
__global__ void __launch_bounds__(256) k_rnn_persist(float* __restrict__ out) {
    extern __shared__ __align__(16) char smem[];
    const uint32_t sA = smem_u32(smem);
    const uint32_t sB = sA + SA_BYTES;
    const int t = threadIdx.x;
    const int lane = t & 31, wid = t >> 5;
    const int warp_m = wid & 1;
    const int warp_n = wid >> 1;
    const int bid = blockIdx.x;
    const int nx = bid & 15, kz = bid >> 4;
    const int n0 = nx * 64;
    const int r = t >> 2, q = t & 3;

    const char* hsrc = (const char*)g_h2 + ((size_t)r * K2 + kz * CH3 + q * 8) * 2;
    const char* wsrc = (const char*)g_whh2 + ((size_t)(n0 + r) * K2 + kz * CH3 + q * 8) * 2;
    const uint32_t sAoff = sA + r * SROW + q * 16;
    const uint32_t sBoff = sB + r * SROW + q * 16;

    const int arow = ((lane >> 3) & 1) * 8 + (lane & 7);
    const int ahalf = (lane >> 4) & 1;
    const int brow = ((lane >> 4) & 1) * 8 + (lane & 7);
    const int bhalf = (lane >> 3) & 1;

    // phase-B mapping: thread owns batch row b_own, k-subgroup grp (32 k each)
    const int b_own = t >> 2;            // 0..63
    const int grp = t & 3;               // 0..3
    const bool owner = ((b_own & 15) == nx);
    char* aW = smem + grp * (64 * SROW) + b_own * SROW;   // term0 base in sA

    // prologue: W slice + initial h slice -> SMEM
#pragma unroll
    for (int i = 0; i < SUBC; i++) cp16(sBoff + i * (64 * SROW), wsrc + i * 64);
#pragma unroll
    for (int i = 0; i < SUBC; i++) cp16(sAoff + i * (64 * SROW), hsrc + i * 64);
    asm volatile("cp.async.commit_group;" ::: "memory");
    asm volatile("cp.async.wait_group 0;" ::: "memory");
    __syncthreads();

    unsigned target = 0;
    for (int s = 0; s < SEQ; s++) {
        float* xs = g_xh + (size_t)s * (BATCH * HID);

        // ---- phase A: mma 64x64 partial, red into xs ----
        float acc[2][2][4];
#pragma unroll
        for (int mt = 0; mt < 2; mt++)
#pragma unroll
            for (int nt = 0; nt < 2; nt++)
#pragma unroll
                for (int e = 0; e < 4; e++) acc[mt][nt][e] = 0.f;

#pragma unroll
        for (int sc = 0; sc < SUBC; sc++) {
#pragma unroll
            for (int kp = 0; kp < 2; kp++) {
                uint32_t af[2][4], bf[4];
#pragma unroll
                for (int mt = 0; mt < 2; mt++)
                    ldmx4(af[mt][0], af[mt][1], af[mt][2], af[mt][3],
                          sA + sc * (64 * SROW) + (warp_m * 32 + mt * 16 + arow) * SROW + ahalf * 16 + kp * 32);
                ldmx4(bf[0], bf[1], bf[2], bf[3],
                      sB + sc * (64 * SROW) + (warp_n * 16 + brow) * SROW + bhalf * 16 + kp * 32);
                mma_bf16(acc[0][0], af[0], &bf[0]);
                mma_bf16(acc[0][1], af[0], &bf[2]);
                mma_bf16(acc[1][0], af[1], &bf[0]);
                mma_bf16(acc[1][1], af[1], &bf[2]);
            }
        }
#pragma unroll
        for (int mt = 0; mt < 2; mt++) {
            int row = warp_m * 32 + mt * 16 + (lane >> 2);
#pragma unroll
            for (int nt = 0; nt < 2; nt++) {
                int col = n0 + warp_n * 16 + nt * 8 + (lane & 3) * 2;
                redadd(&xs[(size_t)row * 1024 + col],     acc[mt][nt][0]);
                redadd(&xs[(size_t)row * 1024 + col + 1], acc[mt][nt][1]);
                redadd(&xs[(size_t)(row + 8) * 1024 + col],     acc[mt][nt][2]);
                redadd(&xs[(size_t)(row + 8) * 1024 + col + 1], acc[mt][nt][3]);
            }
        }

        target += RNN_BLOCKS;
        gsync(target);                    // all red.adds to xs visible

        // ---- phase B: tanh of own slice -> SMEM A tile (+ owner global emits) ----
        const float* xrow = xs + b_own * 1024 + kz * 128 + grp * 32;
#pragma unroll
        for (int ii = 0; ii < 16; ii++) {
            float2 v;
            v.x = __ldcg(&xrow[2 * ii]);
            v.y = __ldcg(&xrow[2 * ii + 1]);
            float h0 = tanhf(v.x), h1 = tanhf(v.y);
            __nv_bfloat16 hi0 = __float2bfloat16(h0);
            __nv_bfloat16 hi1 = __float2bfloat16(h1);
            __nv_bfloat16 lo0 = __float2bfloat16(h0 - __bfloat162float(hi0));
            __nv_bfloat16 lo1 = __float2bfloat16(h1 - __bfloat162float(hi1));
            uint32_t hp, lp;
            ((__nv_bfloat16*)&hp)[0] = hi0; ((__nv_bfloat16*)&hp)[1] = hi1;
            ((__nv_bfloat16*)&lp)[0] = lo0; ((__nv_bfloat16*)&lp)[1] = lo1;
            *(uint32_t*)(aW + ii * 4) = hp;                       // term0 hi (sc=grp)
            *(uint32_t*)(aW + 4 * (64 * SROW) + ii * 4) = hp;     // term1 hi (sc=4+grp)
            *(uint32_t*)(aW + 8 * (64 * SROW) + ii * 4) = lp;     // term2 lo (sc=8+grp)
            if (owner) {
                int j = kz * 128 + grp * 32 + 2 * ii;
                __half2 hh = __floats2half2_rn(h0, h1);
                *(__half2*)&g_hallf[(size_t)(s * BATCH + b_own) * KF1 + j] = hh;
                if (s == SEQ - 1) {
                    float2 hv = make_float2(h0, h1);
                    __stcg((float2*)&out[(size_t)SEQ * BATCH * OUT_DIM + b_own * 1024 + j], hv);
                }
            }
        }
        __syncthreads();                  // sA fully written before next phase A
    }
}

// ---------------- HMMA GEMM: C[M,N] = A @ B^T + bias ----------------
// 128x128 block, 4 warps (2x2) of 64x64. m-fastest. B k-chunk wraps by bkmask.
template<bool FP16>
__global__ void __launch_bounds__(128, 2)
gemm_tc(const char* __restrict__ A2, const char* __restrict__ B2,
        float* __restrict__ C, const float* __restrict__ bias0,
        const float* __restrict__ bias1, int mblocks, int ldc, int nbias,
        int kaElems, int kbElems, int nkt, int bkmask)
{
    extern __shared__ __align__(16) char smem[];
    const uint32_t sBase = smem_u32(smem);
    const int t = threadIdx.x;
    const int lane = t & 31, wid = t >> 5;
    const int warp_m = wid & 1;
    const int warp_n = wid >> 1;

    const int m0 = (blockIdx.x % mblocks) * BM;
    const int n0 = (blockIdx.x / mblocks) * BN;

    uint32_t soffA[4], soffB[4];
    const char *gA[4], *gB[4];
#pragma unroll
    for (int i = 0; i < 4; i++) {
        int c = t + 128 * i;
        int row = c >> 2, q = c & 3;
        soffA[i] = (uint32_t)(row * SROW + q * 16);
        soffB[i] = (uint32_t)(BM * SROW + row * SROW + q * 16);
        gA[i] = A2 + ((size_t)(m0 + row) * kaElems + q * 8) * 2;
        gB[i] = B2 + ((size_t)(n0 + row) * kbElems + q * 8) * 2;
    }

    const int arow = ((lane >> 3) & 1) * 8 + (lane & 7);
    const int ahalf = (lane >> 4) & 1;
    const uint32_t aOff = (uint32_t)((warp_m * 64 + arow) * SROW + ahalf * 16);
    const int brow = ((lane >> 4) & 1) * 8 + (lane & 7);
    const int bhalf = (lane >> 3) & 1;
    const uint32_t bOff = (uint32_t)(BM * SROW + (warp_n * 64 + brow) * SROW + bhalf * 16);

    float acc[4][8][4];
#pragma unroll
    for (int mt = 0; mt < 4; mt++)
#pragma unroll
        for (int nt = 0; nt < 8; nt++)
#pragma unroll
            for (int e = 0; e < 4; e++) acc[mt][nt][e] = 0.f;

#pragma unroll
    for (int p = 0; p < STAGES_TC - 1; p++) {
        uint32_t stg = sBase + p * STG_BYTES_TC;
        size_t ka = (size_t)p * 64;
        size_t kb = (size_t)(p & bkmask) * 64;
#pragma unroll
        for (int i = 0; i < 4; i++) cp16(stg + soffA[i], gA[i] + ka);
#pragma unroll
        for (int i = 0; i < 4; i++) cp16(stg + soffB[i], gB[i] + kb);
        asm volatile("cp.async.commit_group;" ::: "memory");
    }

    for (int kt = 0; kt < nkt; kt++) {
        if (kt < nkt - 2)       asm volatile("cp.async.wait_group 2;" ::: "memory");
        else if (kt == nkt - 2) asm volatile("cp.async.wait_group 1;" ::: "memory");
        else                    asm volatile("cp.async.wait_group 0;" ::: "memory");
        __syncthreads();

        if (kt + 3 < nkt) {
            uint32_t stg2 = sBase + ((kt + 3) & 3) * STG_BYTES_TC;
            size_t ka = (size_t)(kt + 3) * 64;
            size_t kb = (size_t)((kt + 3) & bkmask) * 64;
#pragma unroll
            for (int i = 0; i < 4; i++) cp16(stg2 + soffA[i], gA[i] + ka);
#pragma unroll
            for (int i = 0; i < 4; i++) cp16(stg2 + soffB[i], gB[i] + kb);
            asm volatile("cp.async.commit_group;" ::: "memory");
        }

        const uint32_t stg = sBase + (kt & 3) * STG_BYTES_TC;
#pragma unroll
        for (int kp = 0; kp < 2; kp++) {
            uint32_t af[4][4], bf[4][4];
#pragma unroll
            for (int mt = 0; mt < 4; mt++)
                ldmx4(af[mt][0], af[mt][1], af[mt][2], af[mt][3],
                      stg + aOff + mt * 16 * SROW + kp * 32);
#pragma unroll
            for (int p = 0; p < 4; p++)
                ldmx4(bf[p][0], bf[p][1], bf[p][2], bf[p][3],
                      stg + bOff + p * 16 * SROW + kp * 32);
#pragma unroll
            for (int mt = 0; mt < 4; mt++)
#pragma unroll
                for (int nt = 0; nt < 8; nt++) {
                    if (FP16) mma_fp16(acc[mt][nt], af[mt], &bf[nt >> 1][(nt & 1) * 2]);
                    else      mma_bf16(acc[mt][nt], af[mt], &bf[nt >> 1][(nt & 1) * 2]);
                }
        }
    }

#pragma unroll
    for (int mt = 0; mt < 4; mt++) {
        int row = m0 + warp_m * 64 + mt * 16 + (lane >> 2);
#pragma unroll
        for (int nt = 0; nt < 8; nt++) {
            int col = n0 + warp_n * 64 + nt * 8 + (lane & 3) * 2;
            float b0 = 0.f, b1 = 0.f;
            if (nbias >= 1) { b0 += __ldg(&bias0[col]); b1 += __ldg(&bias0[col + 1]); }
            if (nbias >= 2) { b0 += __ldg(&bias1[col]); b1 += __ldg(&bias1[col + 1]); }
            float2 v0 = make_float2(acc[mt][nt][0] + b0, acc[mt][nt][1] + b1);
            float2 v1 = make_float2(acc[mt][nt][2] + b0, acc[mt][nt][3] + b1);
            *(float2*)&C[(size_t)row * ldc + col] = v0;
            *(float2*)&C[(size_t)(row + 8) * ldc + col] = v1;
        }
    }
}

// ---------------- launch ----------------
extern "C" void kernel_launch(void* const* d_in, const int* in_sizes, int n_in,
                              void* d_out, int out_size)
{
    const void*  x      = d_in[0];
    const float* hidden = (const float*)d_in[1];
    const float* emb    = (const float*)d_in[2];
    const float* W_ih   = (const float*)d_in[3];
    const float* W_hh   = (const float*)d_in[4];
    const float* b_ih   = (const float*)d_in[5];
    const float* b_hh   = (const float*)d_in[6];
    const float* W_fc   = (const float*)d_in[7];
    const float* b_fc   = (const float*)d_in[8];
    float* out = (float*)d_out;

    float* p_xh;
    void *p_hallf, *p_wfcf, *p_wihf, *p_embf;
    cudaGetSymbolAddress((void**)&p_xh, g_xh);
    cudaGetSymbolAddress(&p_hallf, g_hallf);
    cudaGetSymbolAddress(&p_wfcf,  g_wfcf);
    cudaGetSymbolAddress(&p_wihf,  g_wihf);
    cudaGetSymbolAddress(&p_embf,  g_embf);

    cudaFuncSetAttribute(gemm_tc<true>,  cudaFuncAttributeMaxDynamicSharedMemorySize, SMEM_TC);
    cudaFuncSetAttribute(gemm_tc<false>, cudaFuncAttributeMaxDynamicSharedMemorySize, SMEM_TC);
    cudaFuncSetAttribute(k_rnn_persist,  cudaFuncAttributeMaxDynamicSharedMemorySize, SMEM_RNN);

    k_sniff<<<1, 256>>>(x);
    k_decode<<<(SEQ * BATCH + 255) / 256, 256>>>(x);
    k_copyh<<<(BATCH * HID + 255) / 256, 256>>>(hidden);
    k_conv_whh<<<(HID * HID) / 256, 256>>>(W_hh);
    k_convw_f<<<(HID * HID / 4 + 255) / 256, 256>>>(W_ih, (__half*)p_wihf, HID * HID / 4);
    k_convw_f<<<(OUT_DIM * HID / 4 + 255) / 256, 256>>>(W_fc, (__half*)p_wfcf, OUT_DIM * HID / 4);
    k_gather_split<<<SEQ * BATCH, 256>>>(emb);

    // xh = embf @ wihf^T + b_ih + b_hh : fp16 2-term (B wraps), M=8192, N=1024
    {
        int mblocks = (SEQ * BATCH) / BM;   // 64
        int nblocks = HID / BN;             // 8
        gemm_tc<true><<<mblocks * nblocks, 128, SMEM_TC>>>(
            (const char*)p_embf, (const char*)p_wihf, p_xh, b_ih, b_hh,
            mblocks, HID, 2, KE, HID, KE / BKK, 31);
    }

    // recurrence: persistent HMMA kernel (writes final hidden to out tail)
    k_rnn_persist<<<RNN_BLOCKS, 256, SMEM_RNN>>>(out);

    // outputs = hallf @ wfcf^T + b_fc : fp16 1-term, M=8192, N=32000, K=1024
    {
        int mblocks = (SEQ * BATCH) / BM;   // 64
        int nblocks = OUT_DIM / BN;         // 250
        gemm_tc<true><<<mblocks * nblocks, 128, SMEM_TC>>>(
            (const char*)p_hallf, (const char*)p_wfcf, out, b_fc, nullptr,
            mblocks, OUT_DIM, 1, KF1, HID, KF1 / BKK, 0xFF);
    }
}

// round 12
// speedup vs baseline: 1.1947x; 1.1947x over previous
#include <cuda_runtime.h>
#include <cuda_bf16.h>
#include <cuda_fp16.h>
#include <cstdint>
#include <cstddef>

#define SEQ 128
#define BATCH 64
#define EMB 1024
#define HID 1024
#define OUT_DIM 32000
#define VOCAB 32000
#define RNN_BLOCKS 128

// HMMA GEMM config: 128x128 block, 4 warps of 64x64, BK=32, 4 stages
#define KE 2048                  // fp16 2-term (xh path, A side)
#define KF1 1024                 // fp16 1-term (output path)
#define BM 128
#define BN 128
#define BKK 32
#define SROW 80
#define STG_BYTES_TC ((BM + BN) * SROW)
#define STAGES_TC 4
#define SMEM_TC (STAGES_TC * STG_BYTES_TC)       // 81920

// recurrence persistent kernel config
#define K2 3072                  // bf16 3-term chunked (recurrence)
#define CH3 384
#define SUBC 12
#define SA_BYTES (SUBC * 64 * SROW)              // 61440
#define SMEM_RNN (2 * SA_BYTES)                  // 122880

// ---------------- device scratch ----------------
__device__ __align__(16) float g_xh[SEQ * BATCH * HID];               // xh + biases; phase-A reds land here
__device__ __align__(16) float g_h[BATCH * HID];
__device__ __align__(16) __half g_hallf[SEQ * BATCH * KF1];           // 16.8 MB
__device__ __align__(16) __half g_wfcf[OUT_DIM * HID];                // 64 MB
__device__ __align__(16) __half g_wihf[HID * HID];                    // 2 MB
__device__ __align__(16) __half g_embf[SEQ * BATCH * KE];             // 33.5 MB [hi|lo]
__device__ __align__(16) __nv_bfloat16 g_whh2[HID * K2];              // 6 MB [hi|lo|hi] chunked
__device__ __align__(16) __nv_bfloat16 g_h2[BATCH * K2];              // 384KB [hi|hi|lo] chunked
__device__ int g_idx[SEQ * BATCH];
__device__ unsigned g_arrive;

// ---------------- helpers ----------------
__device__ __forceinline__ uint32_t smem_u32(const void* p) {
    uint32_t a;
    asm("{ .reg .u64 t; cvta.to.shared.u64 t, %1; cvt.u32.u64 %0, t; }" : "=r"(a) : "l"(p));
    return a;
}
__device__ __forceinline__ void cp16(uint32_t s, const void* g) {
    asm volatile("cp.async.cg.shared.global [%0], [%1], 16;" :: "r"(s), "l"(g) : "memory");
}
__device__ __forceinline__ void ldmx4(uint32_t& r0, uint32_t& r1, uint32_t& r2, uint32_t& r3, uint32_t addr) {
    asm volatile("ldmatrix.sync.aligned.m8n8.x4.shared.b16 {%0,%1,%2,%3}, [%4];"
                 : "=r"(r0), "=r"(r1), "=r"(r2), "=r"(r3) : "r"(addr));
}
__device__ __forceinline__ void mma_bf16(float* c, const uint32_t* a, const uint32_t* b) {
    asm volatile("mma.sync.aligned.m16n8k16.row.col.f32.bf16.bf16.f32 "
                 "{%0,%1,%2,%3}, {%4,%5,%6,%7}, {%8,%9}, {%0,%1,%2,%3};"
                 : "+f"(c[0]), "+f"(c[1]), "+f"(c[2]), "+f"(c[3])
                 : "r"(a[0]), "r"(a[1]), "r"(a[2]), "r"(a[3]), "r"(b[0]), "r"(b[1]));
}
__device__ __forceinline__ void mma_fp16(float* c, const uint32_t* a, const uint32_t* b) {
    asm volatile("mma.sync.aligned.m16n8k16.row.col.f32.f16.f16.f32 "
                 "{%0,%1,%2,%3}, {%4,%5,%6,%7}, {%8,%9}, {%0,%1,%2,%3};"
                 : "+f"(c[0]), "+f"(c[1]), "+f"(c[2]), "+f"(c[3])
                 : "r"(a[0]), "r"(a[1]), "r"(a[2]), "r"(a[3]), "r"(b[0]), "r"(b[1]));
}
// grid sync: release/acquire monotonic counter
__device__ __forceinline__ void gsync(unsigned target) {
    __syncthreads();
    if (threadIdx.x == 0) {
        asm volatile("red.release.gpu.global.add.u32 [%0], 1;" :: "l"(&g_arrive) : "memory");
        unsigned v;
        do {
            asm volatile("ld.acquire.gpu.global.u32 %0, [%1];" : "=r"(v) : "l"(&g_arrive) : "memory");
        } while (v < target);
    }
    __syncthreads();
}

// ---------------- small kernels ----------------
// fused dtype sniff + index decode (single block)
__global__ void k_prep(const void* x) {
    __shared__ int bad;
    if (threadIdx.x == 0) bad = 0;
    __syncthreads();
    const unsigned long long* p = (const unsigned long long*)x;
    int mybad = 0;
    for (int i = threadIdx.x; i < 4096; i += 256)
        if (p[i] >= (unsigned long long)VOCAB) mybad = 1;
    if (mybad) atomicOr(&bad, 1);
    __syncthreads();
    int is64 = bad ? 0 : 1;
    for (int i = threadIdx.x; i < SEQ * BATCH; i += 256) {
        if (is64) g_idx[i] = (int)((const long long*)x)[i];
        else      g_idx[i] = ((const int*)x)[i];
    }
}
// init h2 (bf16 chunked split [hi|hi|lo]) and reset grid-sync counter
__global__ void k_copyh(const float* __restrict__ hidden) {
    int i = blockIdx.x * 256 + threadIdx.x;
    if (i == 0) g_arrive = 0;
    if (i >= BATCH * HID) return;
    float v = hidden[i];
    g_h[i] = v;
    __nv_bfloat16 hi = __float2bfloat16(v);
    __nv_bfloat16 lo = __float2bfloat16(v - __bfloat162float(hi));
    int b = i >> 10, j = i & 1023;
    int c = j >> 7, o = j & 127;
    __nv_bfloat16* hb = g_h2 + (size_t)b * K2 + c * CH3 + o;
    hb[0] = hi; hb[128] = hi; hb[256] = lo;
}
// W_hh fp32 -> bf16 chunked [hi | lo | hi] per 128-k chunk
__global__ void k_conv_whh(const float* __restrict__ W) {
    int i = blockIdx.x * 256 + threadIdx.x;
    if (i >= HID * HID) return;
    float v = W[i];
    __nv_bfloat16 hi = __float2bfloat16(v);
    __nv_bfloat16 lo = __float2bfloat16(v - __bfloat162float(hi));
    int row = i >> 10, j = i & 1023;
    int c = j >> 7, o = j & 127;
    __nv_bfloat16* b = g_whh2 + (size_t)row * K2 + c * CH3 + o;
    b[0] = hi; b[128] = lo; b[256] = hi;
}
// fp32 -> fp16 (vectorized), for W_fc and W_ih
__global__ void k_convw_f(const float* __restrict__ W, __half* __restrict__ dst, int n4) {
    int i = blockIdx.x * 256 + threadIdx.x;
    if (i >= n4) return;
    float4 v = ((const float4*)W)[i];
    __half2 a = __floats2half2_rn(v.x, v.y);
    __half2 b = __floats2half2_rn(v.z, v.w);
    ((uint2*)dst)[i] = make_uint2(*(uint32_t*)&a, *(uint32_t*)&b);
}
// gather emb rows, split to fp16 segments [hi | lo]
__global__ void k_gather_split(const float* __restrict__ emb) {
    int r = blockIdx.x;
    int t = threadIdx.x;
    long long src = g_idx[r];
    float4 v = ((const float4*)(emb + (size_t)src * 1024))[t];
    __half h0 = __float2half(v.x), h1 = __float2half(v.y);
    __half h2 = __float2half(v.z), h3 = __float2half(v.w);
    __half l0 = __float2half(v.x - __half2float(h0));
    __half l1 = __float2half(v.y - __half2float(h1));
    __half l2 = __float2half(v.z - __half2float(h2));
    __half l3 = __float2half(v.w - __half2float(h3));
    uint2 hp, lp;
    ((__half*)&hp)[0] = h0; ((__half*)&hp)[1] = h1;
    ((__half*)&hp)[2] = h2; ((__half*)&hp)[3] = h3;
    ((__half*)&lp)[0] = l0; ((__half*)&lp)[1] = l1;
    ((__half*)&lp)[2] = l2; ((__half*)&lp)[3] = l3;
    __half* base = g_embf + (size_t)r * KE;
    ((uint2*)base)[t] = hp;
    ((uint2*)(base + 1024))[t] = lp;
}

// ---------------- persistent recurrence (HMMA bf16 3-term) ----------------
// 128 blocks (16 nx x 8 kz) x 256 thr. W slice SMEM-resident all steps.
// Phase A: 64x64 partial -> float2 atomicAdd into g_xh[s] (pre-initialized
// with xh+biases). Phase B: single load + tanh + emits.
__global__ void __launch_bounds__(256) k_rnn_persist(float* __restrict__ out) {
    extern __shared__ __align__(16) char smem[];
    const uint32_t sA = smem_u32(smem);
    const uint32_t sB = sA + SA_BYTES;
    const int t = threadIdx.x;
    const int lane = t & 31, wid = t >> 5;
    const int warp_m = wid & 1;
    const int warp_n = wid >> 1;
    const int bid = blockIdx.x;
    const int nx = bid & 15, kz = bid >> 4;
    const int n0 = nx * 64;
    const int r = t >> 2, q = t & 3;

    const char* hsrc = (const char*)g_h2 + ((size_t)r * K2 + kz * CH3 + q * 8) * 2;
    const char* wsrc = (const char*)g_whh2 + ((size_t)(n0 + r) * K2 + kz * CH3 + q * 8) * 2;
    const uint32_t sAoff = sA + r * SROW + q * 16;
    const uint32_t sBoff = sB + r * SROW + q * 16;

    const int arow = ((lane >> 3) & 1) * 8 + (lane & 7);
    const int ahalf = (lane >> 4) & 1;
    const int brow = ((lane >> 4) & 1) * 8 + (lane & 7);
    const int bhalf = (lane >> 3) & 1;

    const int i0 = bid * 512 + t;

    // W slice -> SMEM once
#pragma unroll
    for (int i = 0; i < SUBC; i++) cp16(sBoff + i * (64 * SROW), wsrc + i * 64);
    asm volatile("cp.async.commit_group;" ::: "memory");
    asm volatile("cp.async.wait_group 0;" ::: "memory");
    __syncthreads();

    unsigned target = 0;
    for (int s = 0; s < SEQ; s++) {
        float* xs = g_xh + (size_t)s * (BATCH * HID);

        // phase A: load h slice, mma 64x64 partial, vector-red into xs
#pragma unroll
        for (int i = 0; i < SUBC; i++) cp16(sAoff + i * (64 * SROW), hsrc + i * 64);
        asm volatile("cp.async.commit_group;" ::: "memory");
        asm volatile("cp.async.wait_group 0;" ::: "memory");
        __syncthreads();

        float acc[2][2][4];
#pragma unroll
        for (int mt = 0; mt < 2; mt++)
#pragma unroll
            for (int nt = 0; nt < 2; nt++)
#pragma unroll
                for (int e = 0; e < 4; e++) acc[mt][nt][e] = 0.f;

#pragma unroll
        for (int sc = 0; sc < SUBC; sc++) {
#pragma unroll
            for (int kp = 0; kp < 2; kp++) {
                uint32_t af[2][4], bf[4];
#pragma unroll
                for (int mt = 0; mt < 2; mt++)
                    ldmx4(af[mt][0], af[mt][1], af[mt][2], af[mt][3],
                          sA + sc * (64 * SROW) + (warp_m * 32 + mt * 16 + arow) * SROW + ahalf * 16 + kp * 32);
                ldmx4(bf[0], bf[1], bf[2], bf[3],
                      sB + sc * (64 * SROW) + (warp_n * 16 + brow) * SROW + bhalf * 16 + kp * 32);
                mma_bf16(acc[0][0], af[0], &bf[0]);
                mma_bf16(acc[0][1], af[0], &bf[2]);
                mma_bf16(acc[1][0], af[1], &bf[0]);
                mma_bf16(acc[1][1], af[1], &bf[2]);
            }
        }
#pragma unroll
        for (int mt = 0; mt < 2; mt++) {
            int row = warp_m * 32 + mt * 16 + (lane >> 2);
#pragma unroll
            for (int nt = 0; nt < 2; nt++) {
                int col = n0 + warp_n * 16 + nt * 8 + (lane & 3) * 2;
                atomicAdd((float2*)&xs[(size_t)row * 1024 + col],
                          make_float2(acc[mt][nt][0], acc[mt][nt][1]));
                atomicAdd((float2*)&xs[(size_t)(row + 8) * 1024 + col],
                          make_float2(acc[mt][nt][2], acc[mt][nt][3]));
            }
        }

        target += RNN_BLOCKS;
        gsync(target);

        // phase B: tanh + emits
#pragma unroll
        for (int e = 0; e < 2; e++) {
            int i = i0 + e * 256;
            float h = tanhf(__ldcg(&xs[i]));
            int b = i >> 10, j = i & 1023;
            g_hallf[(size_t)(s * BATCH + b) * KF1 + j] = __float2half(h);
            __nv_bfloat16 hi = __float2bfloat16(h);
            __nv_bfloat16 lo = __float2bfloat16(h - __bfloat162float(hi));
            int c = j >> 7, o = j & 127;
            __nv_bfloat16* hb = g_h2 + (size_t)b * K2 + c * CH3 + o;
            hb[0] = hi; hb[128] = hi; hb[256] = lo;
            if (s == SEQ - 1) __stcg(&g_h[i], h);
        }

        target += RNN_BLOCKS;
        gsync(target);
    }

    // final hidden -> out tail
#pragma unroll
    for (int e = 0; e < 2; e++) {
        int i = i0 + e * 256;
        out[(size_t)SEQ * BATCH * OUT_DIM + i] = __ldcg(&g_h[i]);
    }
}

// ---------------- HMMA GEMM: C[M,N] = A @ B^T + bias ----------------
// 128x128 block, 4 warps (2x2) of 64x64. m-fastest. B k-chunk wraps by bkmask.
template<bool FP16>
__global__ void __launch_bounds__(128, 2)
gemm_tc(const char* __restrict__ A2, const char* __restrict__ B2,
        float* __restrict__ C, const float* __restrict__ bias0,
        const float* __restrict__ bias1, int mblocks, int ldc, int nbias,
        int kaElems, int kbElems, int nkt, int bkmask)
{
    extern __shared__ __align__(16) char smem[];
    const uint32_t sBase = smem_u32(smem);
    const int t = threadIdx.x;
    const int lane = t & 31, wid = t >> 5;
    const int warp_m = wid & 1;
    const int warp_n = wid >> 1;

    const int m0 = (blockIdx.x % mblocks) * BM;
    const int n0 = (blockIdx.x / mblocks) * BN;

    uint32_t soffA[4], soffB[4];
    const char *gA[4], *gB[4];
#pragma unroll
    for (int i = 0; i < 4; i++) {
        int c = t + 128 * i;
        int row = c >> 2, q = c & 3;
        soffA[i] = (uint32_t)(row * SROW + q * 16);
        soffB[i] = (uint32_t)(BM * SROW + row * SROW + q * 16);
        gA[i] = A2 + ((size_t)(m0 + row) * kaElems + q * 8) * 2;
        gB[i] = B2 + ((size_t)(n0 + row) * kbElems + q * 8) * 2;
    }

    const int arow = ((lane >> 3) & 1) * 8 + (lane & 7);
    const int ahalf = (lane >> 4) & 1;
    const uint32_t aOff = (uint32_t)((warp_m * 64 + arow) * SROW + ahalf * 16);
    const int brow = ((lane >> 4) & 1) * 8 + (lane & 7);
    const int bhalf = (lane >> 3) & 1;
    const uint32_t bOff = (uint32_t)(BM * SROW + (warp_n * 64 + brow) * SROW + bhalf * 16);

    float acc[4][8][4];
#pragma unroll
    for (int mt = 0; mt < 4; mt++)
#pragma unroll
        for (int nt = 0; nt < 8; nt++)
#pragma unroll
            for (int e = 0; e < 4; e++) acc[mt][nt][e] = 0.f;

#pragma unroll
    for (int p = 0; p < STAGES_TC - 1; p++) {
        uint32_t stg = sBase + p * STG_BYTES_TC;
        size_t ka = (size_t)p * 64;
        size_t kb = (size_t)(p & bkmask) * 64;
#pragma unroll
        for (int i = 0; i < 4; i++) cp16(stg + soffA[i], gA[i] + ka);
#pragma unroll
        for (int i = 0; i < 4; i++) cp16(stg + soffB[i], gB[i] + kb);
        asm volatile("cp.async.commit_group;" ::: "memory");
    }

    for (int kt = 0; kt < nkt; kt++) {
        if (kt < nkt - 2)       asm volatile("cp.async.wait_group 2;" ::: "memory");
        else if (kt == nkt - 2) asm volatile("cp.async.wait_group 1;" ::: "memory");
        else                    asm volatile("cp.async.wait_group 0;" ::: "memory");
        __syncthreads();

        if (kt + 3 < nkt) {
            uint32_t stg2 = sBase + ((kt + 3) & 3) * STG_BYTES_TC;
            size_t ka = (size_t)(kt + 3) * 64;
            size_t kb = (size_t)((kt + 3) & bkmask) * 64;
#pragma unroll
            for (int i = 0; i < 4; i++) cp16(stg2 + soffA[i], gA[i] + ka);
#pragma unroll
            for (int i = 0; i < 4; i++) cp16(stg2 + soffB[i], gB[i] + kb);
            asm volatile("cp.async.commit_group;" ::: "memory");
        }

        const uint32_t stg = sBase + (kt & 3) * STG_BYTES_TC;
#pragma unroll
        for (int kp = 0; kp < 2; kp++) {
            uint32_t af[4][4], bf[4][4];
#pragma unroll
            for (int mt = 0; mt < 4; mt++)
                ldmx4(af[mt][0], af[mt][1], af[mt][2], af[mt][3],
                      stg + aOff + mt * 16 * SROW + kp * 32);
#pragma unroll
            for (int p = 0; p < 4; p++)
                ldmx4(bf[p][0], bf[p][1], bf[p][2], bf[p][3],
                      stg + bOff + p * 16 * SROW + kp * 32);
#pragma unroll
            for (int mt = 0; mt < 4; mt++)
#pragma unroll
                for (int nt = 0; nt < 8; nt++) {
                    if (FP16) mma_fp16(acc[mt][nt], af[mt], &bf[nt >> 1][(nt & 1) * 2]);
                    else      mma_bf16(acc[mt][nt], af[mt], &bf[nt >> 1][(nt & 1) * 2]);
                }
        }
    }

#pragma unroll
    for (int mt = 0; mt < 4; mt++) {
        int row = m0 + warp_m * 64 + mt * 16 + (lane >> 2);
#pragma unroll
        for (int nt = 0; nt < 8; nt++) {
            int col = n0 + warp_n * 64 + nt * 8 + (lane & 3) * 2;
            float b0 = 0.f, b1 = 0.f;
            if (nbias >= 1) { b0 += __ldg(&bias0[col]); b1 += __ldg(&bias0[col + 1]); }
            if (nbias >= 2) { b0 += __ldg(&bias1[col]); b1 += __ldg(&bias1[col + 1]); }
            float2 v0 = make_float2(acc[mt][nt][0] + b0, acc[mt][nt][1] + b1);
            float2 v1 = make_float2(acc[mt][nt][2] + b0, acc[mt][nt][3] + b1);
            *(float2*)&C[(size_t)row * ldc + col] = v0;
            *(float2*)&C[(size_t)(row + 8) * ldc + col] = v1;
        }
    }
}

// ---------------- launch ----------------
extern "C" void kernel_launch(void* const* d_in, const int* in_sizes, int n_in,
                              void* d_out, int out_size)
{
    const void*  x      = d_in[0];
    const float* hidden = (const float*)d_in[1];
    const float* emb    = (const float*)d_in[2];
    const float* W_ih   = (const float*)d_in[3];
    const float* W_hh   = (const float*)d_in[4];
    const float* b_ih   = (const float*)d_in[5];
    const float* b_hh   = (const float*)d_in[6];
    const float* W_fc   = (const float*)d_in[7];
    const float* b_fc   = (const float*)d_in[8];
    float* out = (float*)d_out;

    float* p_xh;
    void *p_hallf, *p_wfcf, *p_wihf, *p_embf;
    cudaGetSymbolAddress((void**)&p_xh, g_xh);
    cudaGetSymbolAddress(&p_hallf, g_hallf);
    cudaGetSymbolAddress(&p_wfcf,  g_wfcf);
    cudaGetSymbolAddress(&p_wihf,  g_wihf);
    cudaGetSymbolAddress(&p_embf,  g_embf);

    cudaFuncSetAttribute(gemm_tc<true>,  cudaFuncAttributeMaxDynamicSharedMemorySize, SMEM_TC);
    cudaFuncSetAttribute(gemm_tc<false>, cudaFuncAttributeMaxDynamicSharedMemorySize, SMEM_TC);
    cudaFuncSetAttribute(k_rnn_persist,  cudaFuncAttributeMaxDynamicSharedMemorySize, SMEM_RNN);

    k_prep<<<1, 256>>>(x);
    k_copyh<<<(BATCH * HID + 255) / 256, 256>>>(hidden);
    k_conv_whh<<<(HID * HID) / 256, 256>>>(W_hh);
    k_convw_f<<<(HID * HID / 4 + 255) / 256, 256>>>(W_ih, (__half*)p_wihf, HID * HID / 4);
    k_convw_f<<<(OUT_DIM * HID / 4 + 255) / 256, 256>>>(W_fc, (__half*)p_wfcf, OUT_DIM * HID / 4);
    k_gather_split<<<SEQ * BATCH, 256>>>(emb);

    // xh = embf @ wihf^T + b_ih + b_hh : fp16 2-term (B wraps), M=8192, N=1024
    {
        int mblocks = (SEQ * BATCH) / BM;   // 64
        int nblocks = HID / BN;             // 8
        gemm_tc<true><<<mblocks * nblocks, 128, SMEM_TC>>>(
            (const char*)p_embf, (const char*)p_wihf, p_xh, b_ih, b_hh,
            mblocks, HID, 2, KE, HID, KE / BKK, 31);
    }

    // recurrence: persistent HMMA kernel (writes final hidden to out tail)
    k_rnn_persist<<<RNN_BLOCKS, 256, SMEM_RNN>>>(out);

    // outputs = hallf @ wfcf^T + b_fc : fp16 1-term, M=8192, N=32000, K=1024
    {
        int mblocks = (SEQ * BATCH) / BM;   // 64
        int nblocks = OUT_DIM / BN;         // 250
        gemm_tc<true><<<mblocks * nblocks, 128, SMEM_TC>>>(
            (const char*)p_hallf, (const char*)p_wfcf, out, b_fc, nullptr,
            mblocks, OUT_DIM, 1, KF1, HID, KF1 / BKK, 0xFF);
    }
}

// round 13
// speedup vs baseline: 1.2285x; 1.0283x over previous
#include <cuda_runtime.h>
#include <cuda_bf16.h>
#include <cuda_fp16.h>
#include <cstdint>
#include <cstddef>

#define SEQ 128
#define BATCH 64
#define EMB 1024
#define HID 1024
#define OUT_DIM 32000
#define VOCAB 32000
#define RNN_BLOCKS 128
#define NCH 8                    // overlap chunks (16 steps each)
#define CH_STEPS (SEQ / NCH)     // 16
#define CH_ROWS (CH_STEPS * BATCH)   // 1024 output rows per chunk

// HMMA GEMM config: 128x128 block, 4 warps of 64x64, BK=32, 4 stages
#define KE 2048                  // fp16 2-term (xh path, A side)
#define KF1 1024                 // fp16 1-term (output path)
#define BM 128
#define BN 128
#define BKK 32
#define SROW 80
#define STG_BYTES_TC ((BM + BN) * SROW)
#define STAGES_TC 4
#define SMEM_TC (STAGES_TC * STG_BYTES_TC)       // 81920

// recurrence persistent kernel config
#define K2 3072                  // bf16 3-term chunked (recurrence)
#define CH3 384
#define SUBC 12
#define SA_BYTES (SUBC * 64 * SROW)              // 61440
#define SMEM_RNN (2 * SA_BYTES)                  // 122880

// ---------------- device scratch ----------------
__device__ __align__(16) float g_xh[SEQ * BATCH * HID];               // xh + biases; phase-A reds land here
__device__ __align__(16) float g_h[BATCH * HID];
__device__ __align__(16) __half g_hallf[SEQ * BATCH * KF1];           // 16.8 MB
__device__ __align__(16) __half g_wfcf[OUT_DIM * HID];                // 64 MB
__device__ __align__(16) __half g_wihf[HID * HID];                    // 2 MB
__device__ __align__(16) __half g_embf[SEQ * BATCH * KE];             // 33.5 MB [hi|lo]
__device__ __align__(16) __nv_bfloat16 g_whh2[HID * K2];              // 6 MB [hi|lo|hi] chunked
__device__ __align__(16) __nv_bfloat16 g_h2[BATCH * K2];              // 384KB [hi|hi|lo] chunked
__device__ int g_idx[SEQ * BATCH];
__device__ unsigned g_arrive;

// ---------------- helpers ----------------
__device__ __forceinline__ uint32_t smem_u32(const void* p) {
    uint32_t a;
    asm("{ .reg .u64 t; cvta.to.shared.u64 t, %1; cvt.u32.u64 %0, t; }" : "=r"(a) : "l"(p));
    return a;
}
__device__ __forceinline__ void cp16(uint32_t s, const void* g) {
    asm volatile("cp.async.cg.shared.global [%0], [%1], 16;" :: "r"(s), "l"(g) : "memory");
}
__device__ __forceinline__ void ldmx4(uint32_t& r0, uint32_t& r1, uint32_t& r2, uint32_t& r3, uint32_t addr) {
    asm volatile("ldmatrix.sync.aligned.m8n8.x4.shared.b16 {%0,%1,%2,%3}, [%4];"
                 : "=r"(r0), "=r"(r1), "=r"(r2), "=r"(r3) : "r"(addr));
}
__device__ __forceinline__ void mma_bf16(float* c, const uint32_t* a, const uint32_t* b) {
    asm volatile("mma.sync.aligned.m16n8k16.row.col.f32.bf16.bf16.f32 "
                 "{%0,%1,%2,%3}, {%4,%5,%6,%7}, {%8,%9}, {%0,%1,%2,%3};"
                 : "+f"(c[0]), "+f"(c[1]), "+f"(c[2]), "+f"(c[3])
                 : "r"(a[0]), "r"(a[1]), "r"(a[2]), "r"(a[3]), "r"(b[0]), "r"(b[1]));
}
__device__ __forceinline__ void mma_fp16(float* c, const uint32_t* a, const uint32_t* b) {
    asm volatile("mma.sync.aligned.m16n8k16.row.col.f32.f16.f16.f32 "
                 "{%0,%1,%2,%3}, {%4,%5,%6,%7}, {%8,%9}, {%0,%1,%2,%3};"
                 : "+f"(c[0]), "+f"(c[1]), "+f"(c[2]), "+f"(c[3])
                 : "r"(a[0]), "r"(a[1]), "r"(a[2]), "r"(a[3]), "r"(b[0]), "r"(b[1]));
}
// grid sync: release/acquire monotonic counter
__device__ __forceinline__ void gsync(unsigned target) {
    __syncthreads();
    if (threadIdx.x == 0) {
        asm volatile("red.release.gpu.global.add.u32 [%0], 1;" :: "l"(&g_arrive) : "memory");
        unsigned v;
        do {
            asm volatile("ld.acquire.gpu.global.u32 %0, [%1];" : "=r"(v) : "l"(&g_arrive) : "memory");
        } while (v < target);
    }
    __syncthreads();
}

// ---------------- small kernels ----------------
// fused dtype sniff + index decode (single block)
__global__ void k_prep(const void* x) {
    __shared__ int bad;
    if (threadIdx.x == 0) bad = 0;
    __syncthreads();
    const unsigned long long* p = (const unsigned long long*)x;
    int mybad = 0;
    for (int i = threadIdx.x; i < 4096; i += 256)
        if (p[i] >= (unsigned long long)VOCAB) mybad = 1;
    if (mybad) atomicOr(&bad, 1);
    __syncthreads();
    int is64 = bad ? 0 : 1;
    for (int i = threadIdx.x; i < SEQ * BATCH; i += 256) {
        if (is64) g_idx[i] = (int)((const long long*)x)[i];
        else      g_idx[i] = ((const int*)x)[i];
    }
}
// init h2 (bf16 chunked split [hi|hi|lo]) and reset grid-sync counter
__global__ void k_copyh(const float* __restrict__ hidden) {
    int i = blockIdx.x * 256 + threadIdx.x;
    if (i == 0) g_arrive = 0;
    if (i >= BATCH * HID) return;
    float v = hidden[i];
    g_h[i] = v;
    __nv_bfloat16 hi = __float2bfloat16(v);
    __nv_bfloat16 lo = __float2bfloat16(v - __bfloat162float(hi));
    int b = i >> 10, j = i & 1023;
    int c = j >> 7, o = j & 127;
    __nv_bfloat16* hb = g_h2 + (size_t)b * K2 + c * CH3 + o;
    hb[0] = hi; hb[128] = hi; hb[256] = lo;
}
// W_hh fp32 -> bf16 chunked [hi | lo | hi] per 128-k chunk
__global__ void k_conv_whh(const float* __restrict__ W) {
    int i = blockIdx.x * 256 + threadIdx.x;
    if (i >= HID * HID) return;
    float v = W[i];
    __nv_bfloat16 hi = __float2bfloat16(v);
    __nv_bfloat16 lo = __float2bfloat16(v - __bfloat162float(hi));
    int row = i >> 10, j = i & 1023;
    int c = j >> 7, o = j & 127;
    __nv_bfloat16* b = g_whh2 + (size_t)row * K2 + c * CH3 + o;
    b[0] = hi; b[128] = lo; b[256] = hi;
}
// fp32 -> fp16 (vectorized), for W_fc and W_ih
__global__ void k_convw_f(const float* __restrict__ W, __half* __restrict__ dst, int n4) {
    int i = blockIdx.x * 256 + threadIdx.x;
    if (i >= n4) return;
    float4 v = ((const float4*)W)[i];
    __half2 a = __floats2half2_rn(v.x, v.y);
    __half2 b = __floats2half2_rn(v.z, v.w);
    ((uint2*)dst)[i] = make_uint2(*(uint32_t*)&a, *(uint32_t*)&b);
}
// gather emb rows, split to fp16 segments [hi | lo]
__global__ void k_gather_split(const float* __restrict__ emb) {
    int r = blockIdx.x;
    int t = threadIdx.x;
    long long src = g_idx[r];
    float4 v = ((const float4*)(emb + (size_t)src * 1024))[t];
    __half h0 = __float2half(v.x), h1 = __float2half(v.y);
    __half h2 = __float2half(v.z), h3 = __float2half(v.w);
    __half l0 = __float2half(v.x - __half2float(h0));
    __half l1 = __float2half(v.y - __half2float(h1));
    __half l2 = __float2half(v.z - __half2float(h2));
    __half l3 = __float2half(v.w - __half2float(h3));
    uint2 hp, lp;
    ((__half*)&hp)[0] = h0; ((__half*)&hp)[1] = h1;
    ((__half*)&hp)[2] = h2; ((__half*)&hp)[3] = h3;
    ((__half*)&lp)[0] = l0; ((__half*)&lp)[1] = l1;
    ((__half*)&lp)[2] = l2; ((__half*)&lp)[3] = l3;
    __half* base = g_embf + (size_t)r * KE;
    ((uint2*)base)[t] = hp;
    ((uint2*)(base + 1024))[t] = lp;
}

// ---------------- persistent recurrence (HMMA bf16 3-term, chunked) ----------------
// 128 blocks (16 nx x 8 kz) x 256 thr. W slice SMEM-resident per chunk.
// Runs steps [s_begin, s_end); gsync counter is monotonic across chunk launches
// (absolute targets derived from step index). Phase A: 64x64 partial -> float2
// atomicAdd into g_xh[s]. Phase B: tanh + emits to g_hallf / g_h2.
__global__ void __launch_bounds__(256) k_rnn_persist(float* __restrict__ out,
                                                     int s_begin, int s_end,
                                                     unsigned tbase, int writeTail) {
    extern __shared__ __align__(16) char smem[];
    const uint32_t sA = smem_u32(smem);
    const uint32_t sB = sA + SA_BYTES;
    const int t = threadIdx.x;
    const int lane = t & 31, wid = t >> 5;
    const int warp_m = wid & 1;
    const int warp_n = wid >> 1;
    const int bid = blockIdx.x;
    const int nx = bid & 15, kz = bid >> 4;
    const int n0 = nx * 64;
    const int r = t >> 2, q = t & 3;

    const char* hsrc = (const char*)g_h2 + ((size_t)r * K2 + kz * CH3 + q * 8) * 2;
    const char* wsrc = (const char*)g_whh2 + ((size_t)(n0 + r) * K2 + kz * CH3 + q * 8) * 2;
    const uint32_t sAoff = sA + r * SROW + q * 16;
    const uint32_t sBoff = sB + r * SROW + q * 16;

    const int arow = ((lane >> 3) & 1) * 8 + (lane & 7);
    const int ahalf = (lane >> 4) & 1;
    const int brow = ((lane >> 4) & 1) * 8 + (lane & 7);
    const int bhalf = (lane >> 3) & 1;

    const int i0 = bid * 512 + t;

    // W slice -> SMEM once per chunk
#pragma unroll
    for (int i = 0; i < SUBC; i++) cp16(sBoff + i * (64 * SROW), wsrc + i * 64);
    asm volatile("cp.async.commit_group;" ::: "memory");
    asm volatile("cp.async.wait_group 0;" ::: "memory");
    __syncthreads();

    unsigned target = tbase;
    for (int s = s_begin; s < s_end; s++) {
        float* xs = g_xh + (size_t)s * (BATCH * HID);

        // phase A: load h slice, mma 64x64 partial, vector-red into xs
#pragma unroll
        for (int i = 0; i < SUBC; i++) cp16(sAoff + i * (64 * SROW), hsrc + i * 64);
        asm volatile("cp.async.commit_group;" ::: "memory");
        asm volatile("cp.async.wait_group 0;" ::: "memory");
        __syncthreads();

        float acc[2][2][4];
#pragma unroll
        for (int mt = 0; mt < 2; mt++)
#pragma unroll
            for (int nt = 0; nt < 2; nt++)
#pragma unroll
                for (int e = 0; e < 4; e++) acc[mt][nt][e] = 0.f;

#pragma unroll
        for (int sc = 0; sc < SUBC; sc++) {
#pragma unroll
            for (int kp = 0; kp < 2; kp++) {
                uint32_t af[2][4], bf[4];
#pragma unroll
                for (int mt = 0; mt < 2; mt++)
                    ldmx4(af[mt][0], af[mt][1], af[mt][2], af[mt][3],
                          sA + sc * (64 * SROW) + (warp_m * 32 + mt * 16 + arow) * SROW + ahalf * 16 + kp * 32);
                ldmx4(bf[0], bf[1], bf[2], bf[3],
                      sB + sc * (64 * SROW) + (warp_n * 16 + brow) * SROW + bhalf * 16 + kp * 32);
                mma_bf16(acc[0][0], af[0], &bf[0]);
                mma_bf16(acc[0][1], af[0], &bf[2]);
                mma_bf16(acc[1][0], af[1], &bf[0]);
                mma_bf16(acc[1][1], af[1], &bf[2]);
            }
        }
#pragma unroll
        for (int mt = 0; mt < 2; mt++) {
            int row = warp_m * 32 + mt * 16 + (lane >> 2);
#pragma unroll
            for (int nt = 0; nt < 2; nt++) {
                int col = n0 + warp_n * 16 + nt * 8 + (lane & 3) * 2;
                atomicAdd((float2*)&xs[(size_t)row * 1024 + col],
                          make_float2(acc[mt][nt][0], acc[mt][nt][1]));
                atomicAdd((float2*)&xs[(size_t)(row + 8) * 1024 + col],
                          make_float2(acc[mt][nt][2], acc[mt][nt][3]));
            }
        }

        target += RNN_BLOCKS;
        gsync(target);

        // phase B: tanh + emits
#pragma unroll
        for (int e = 0; e < 2; e++) {
            int i = i0 + e * 256;
            float h = tanhf(__ldcg(&xs[i]));
            int b = i >> 10, j = i & 1023;
            g_hallf[(size_t)(s * BATCH + b) * KF1 + j] = __float2half(h);
            __nv_bfloat16 hi = __float2bfloat16(h);
            __nv_bfloat16 lo = __float2bfloat16(h - __bfloat162float(hi));
            int c = j >> 7, o = j & 127;
            __nv_bfloat16* hb = g_h2 + (size_t)b * K2 + c * CH3 + o;
            hb[0] = hi; hb[128] = hi; hb[256] = lo;
            if (s == SEQ - 1) __stcg(&g_h[i], h);
        }

        target += RNN_BLOCKS;
        gsync(target);
    }

    // final hidden -> out tail (last chunk only)
    if (writeTail) {
#pragma unroll
        for (int e = 0; e < 2; e++) {
            int i = i0 + e * 256;
            out[(size_t)SEQ * BATCH * OUT_DIM + i] = __ldcg(&g_h[i]);
        }
    }
}

// ---------------- HMMA GEMM: C[M,N] = A @ B^T + bias ----------------
// 128x128 block, 4 warps (2x2) of 64x64. m-fastest. B k-chunk wraps by bkmask.
template<bool FP16>
__global__ void __launch_bounds__(128, 2)
gemm_tc(const char* __restrict__ A2, const char* __restrict__ B2,
        float* __restrict__ C, const float* __restrict__ bias0,
        const float* __restrict__ bias1, int mblocks, int ldc, int nbias,
        int kaElems, int kbElems, int nkt, int bkmask)
{
    extern __shared__ __align__(16) char smem[];
    const uint32_t sBase = smem_u32(smem);
    const int t = threadIdx.x;
    const int lane = t & 31, wid = t >> 5;
    const int warp_m = wid & 1;
    const int warp_n = wid >> 1;

    const int m0 = (blockIdx.x % mblocks) * BM;
    const int n0 = (blockIdx.x / mblocks) * BN;

    uint32_t soffA[4], soffB[4];
    const char *gA[4], *gB[4];
#pragma unroll
    for (int i = 0; i < 4; i++) {
        int c = t + 128 * i;
        int row = c >> 2, q = c & 3;
        soffA[i] = (uint32_t)(row * SROW + q * 16);
        soffB[i] = (uint32_t)(BM * SROW + row * SROW + q * 16);
        gA[i] = A2 + ((size_t)(m0 + row) * kaElems + q * 8) * 2;
        gB[i] = B2 + ((size_t)(n0 + row) * kbElems + q * 8) * 2;
    }

    const int arow = ((lane >> 3) & 1) * 8 + (lane & 7);
    const int ahalf = (lane >> 4) & 1;
    const uint32_t aOff = (uint32_t)((warp_m * 64 + arow) * SROW + ahalf * 16);
    const int brow = ((lane >> 4) & 1) * 8 + (lane & 7);
    const int bhalf = (lane >> 3) & 1;
    const uint32_t bOff = (uint32_t)(BM * SROW + (warp_n * 64 + brow) * SROW + bhalf * 16);

    float acc[4][8][4];
#pragma unroll
    for (int mt = 0; mt < 4; mt++)
#pragma unroll
        for (int nt = 0; nt < 8; nt++)
#pragma unroll
            for (int e = 0; e < 4; e++) acc[mt][nt][e] = 0.f;

#pragma unroll
    for (int p = 0; p < STAGES_TC - 1; p++) {
        uint32_t stg = sBase + p * STG_BYTES_TC;
        size_t ka = (size_t)p * 64;
        size_t kb = (size_t)(p & bkmask) * 64;
#pragma unroll
        for (int i = 0; i < 4; i++) cp16(stg + soffA[i], gA[i] + ka);
#pragma unroll
        for (int i = 0; i < 4; i++) cp16(stg + soffB[i], gB[i] + kb);
        asm volatile("cp.async.commit_group;" ::: "memory");
    }

    for (int kt = 0; kt < nkt; kt++) {
        if (kt < nkt - 2)       asm volatile("cp.async.wait_group 2;" ::: "memory");
        else if (kt == nkt - 2) asm volatile("cp.async.wait_group 1;" ::: "memory");
        else                    asm volatile("cp.async.wait_group 0;" ::: "memory");
        __syncthreads();

        if (kt + 3 < nkt) {
            uint32_t stg2 = sBase + ((kt + 3) & 3) * STG_BYTES_TC;
            size_t ka = (size_t)(kt + 3) * 64;
            size_t kb = (size_t)((kt + 3) & bkmask) * 64;
#pragma unroll
            for (int i = 0; i < 4; i++) cp16(stg2 + soffA[i], gA[i] + ka);
#pragma unroll
            for (int i = 0; i < 4; i++) cp16(stg2 + soffB[i], gB[i] + kb);
            asm volatile("cp.async.commit_group;" ::: "memory");
        }

        const uint32_t stg = sBase + (kt & 3) * STG_BYTES_TC;
#pragma unroll
        for (int kp = 0; kp < 2; kp++) {
            uint32_t af[4][4], bf[4][4];
#pragma unroll
            for (int mt = 0; mt < 4; mt++)
                ldmx4(af[mt][0], af[mt][1], af[mt][2], af[mt][3],
                      stg + aOff + mt * 16 * SROW + kp * 32);
#pragma unroll
            for (int p = 0; p < 4; p++)
                ldmx4(bf[p][0], bf[p][1], bf[p][2], bf[p][3],
                      stg + bOff + p * 16 * SROW + kp * 32);
#pragma unroll
            for (int mt = 0; mt < 4; mt++)
#pragma unroll
                for (int nt = 0; nt < 8; nt++) {
                    if (FP16) mma_fp16(acc[mt][nt], af[mt], &bf[nt >> 1][(nt & 1) * 2]);
                    else      mma_bf16(acc[mt][nt], af[mt], &bf[nt >> 1][(nt & 1) * 2]);
                }
        }
    }

#pragma unroll
    for (int mt = 0; mt < 4; mt++) {
        int row = m0 + warp_m * 64 + mt * 16 + (lane >> 2);
#pragma unroll
        for (int nt = 0; nt < 8; nt++) {
            int col = n0 + warp_n * 64 + nt * 8 + (lane & 3) * 2;
            float b0 = 0.f, b1 = 0.f;
            if (nbias >= 1) { b0 += __ldg(&bias0[col]); b1 += __ldg(&bias0[col + 1]); }
            if (nbias >= 2) { b0 += __ldg(&bias1[col]); b1 += __ldg(&bias1[col + 1]); }
            float2 v0 = make_float2(acc[mt][nt][0] + b0, acc[mt][nt][1] + b1);
            float2 v1 = make_float2(acc[mt][nt][2] + b0, acc[mt][nt][3] + b1);
            *(float2*)&C[(size_t)row * ldc + col] = v0;
            *(float2*)&C[(size_t)(row + 8) * ldc + col] = v1;
        }
    }
}

// ---------------- launch ----------------
extern "C" void kernel_launch(void* const* d_in, const int* in_sizes, int n_in,
                              void* d_out, int out_size)
{
    const void*  x      = d_in[0];
    const float* hidden = (const float*)d_in[1];
    const float* emb    = (const float*)d_in[2];
    const float* W_ih   = (const float*)d_in[3];
    const float* W_hh   = (const float*)d_in[4];
    const float* b_ih   = (const float*)d_in[5];
    const float* b_hh   = (const float*)d_in[6];
    const float* W_fc   = (const float*)d_in[7];
    const float* b_fc   = (const float*)d_in[8];
    float* out = (float*)d_out;

    float* p_xh;
    void *p_hallf, *p_wfcf, *p_wihf, *p_embf;
    cudaGetSymbolAddress((void**)&p_xh, g_xh);
    cudaGetSymbolAddress(&p_hallf, g_hallf);
    cudaGetSymbolAddress(&p_wfcf,  g_wfcf);
    cudaGetSymbolAddress(&p_wihf,  g_wihf);
    cudaGetSymbolAddress(&p_embf,  g_embf);

    cudaFuncSetAttribute(gemm_tc<true>,  cudaFuncAttributeMaxDynamicSharedMemorySize, SMEM_TC);
    cudaFuncSetAttribute(gemm_tc<false>, cudaFuncAttributeMaxDynamicSharedMemorySize, SMEM_TC);
    cudaFuncSetAttribute(k_rnn_persist,  cudaFuncAttributeMaxDynamicSharedMemorySize, SMEM_RNN);

    // side stream for the output GEMM chunks (+ W_fc convert), joined at end.
    cudaStream_t gs;
    cudaStreamCreateWithFlags(&gs, cudaStreamNonBlocking);
    cudaEvent_t evRoot, evJoin, evF[NCH];
    cudaEventCreateWithFlags(&evRoot, cudaEventDisableTiming);
    cudaEventCreateWithFlags(&evJoin, cudaEventDisableTiming);
    for (int c = 0; c < NCH; c++) cudaEventCreateWithFlags(&evF[c], cudaEventDisableTiming);

    // fork side stream into the capture; run W_fc convert there (overlaps prep/xh/rec0)
    cudaEventRecord(evRoot, 0);
    cudaStreamWaitEvent(gs, evRoot, 0);
    k_convw_f<<<(OUT_DIM * HID / 4 + 255) / 256, 256, 0, gs>>>(W_fc, (__half*)p_wfcf, OUT_DIM * HID / 4);

    // main stream: prep + converts + xh GEMM
    k_prep<<<1, 256>>>(x);
    k_copyh<<<(BATCH * HID + 255) / 256, 256>>>(hidden);
    k_conv_whh<<<(HID * HID) / 256, 256>>>(W_hh);
    k_convw_f<<<(HID * HID / 4 + 255) / 256, 256>>>(W_ih, (__half*)p_wihf, HID * HID / 4);
    k_gather_split<<<SEQ * BATCH, 256>>>(emb);

    // xh = embf @ wihf^T + b_ih + b_hh : fp16 2-term (B wraps), M=8192, N=1024
    gemm_tc<true><<<64 * (HID / BN), 128, SMEM_TC>>>(
        (const char*)p_embf, (const char*)p_wihf, p_xh, b_ih, b_hh,
        64, HID, 2, KE, HID, KE / BKK, 31);

    // recurrence chunks on main; per-chunk output GEMM forked onto gs
    for (int c = 0; c < NCH; c++) {
        int s0 = c * CH_STEPS;
        k_rnn_persist<<<RNN_BLOCKS, 256, SMEM_RNN>>>(
            out, s0, s0 + CH_STEPS, (unsigned)(2 * s0 * RNN_BLOCKS), c == NCH - 1);
        cudaEventRecord(evF[c], 0);
        cudaStreamWaitEvent(gs, evF[c], 0);
        // outputs rows [c*1024, (c+1)*1024) = hallf chunk @ wfcf^T + b_fc
        gemm_tc<true><<<(CH_ROWS / BM) * (OUT_DIM / BN), 128, SMEM_TC, gs>>>(
            (const char*)p_hallf + (size_t)c * CH_ROWS * KF1 * 2,
            (const char*)p_wfcf,
            out + (size_t)c * CH_ROWS * OUT_DIM,
            b_fc, nullptr,
            CH_ROWS / BM, OUT_DIM, 1, KF1, HID, KF1 / BKK, 0xFF);
    }

    // join side stream back into the capture/origin stream
    cudaEventRecord(evJoin, gs);
    cudaStreamWaitEvent(0, evJoin, 0);
}

// round 14
// speedup vs baseline: 1.3512x; 1.0999x over previous
#include <cuda_runtime.h>
#include <cuda_bf16.h>
#include <cuda_fp16.h>
#include <cstdint>
#include <cstddef>

#define SEQ 128
#define BATCH 64
#define EMB 1024
#define HID 1024
#define OUT_DIM 32000
#define VOCAB 32000
#define RNN_BLOCKS 128
#define NCH 8                    // overlap chunks (16 steps each)
#define CH_STEPS (SEQ / NCH)     // 16
#define CH_ROWS (CH_STEPS * BATCH)   // 1024 output rows per chunk

// HMMA GEMM config: 128x128 block, 4 warps of 64x64, BK=32, 4 stages
#define KE 2048                  // fp16 2-term (xh path, A side)
#define KF1 1024                 // fp16 1-term (output path)
#define BM 128
#define BN 128
#define BKK 32
#define SROW 80
#define STG_BYTES_TC ((BM + BN) * SROW)
#define STAGES_TC 4
#define SMEM_TC (STAGES_TC * STG_BYTES_TC)       // 81920

// recurrence persistent kernel config (dedup [hi|lo] operands)
#define K2H 2048                 // bf16 per row: 8 chunks x [hi(128)|lo(128)]
#define SUBL 8                   // physical k32 subchunks per block slice
#define SA_BYTES (SUBL * 64 * SROW)              // 40960
#define SMEM_RNN (2 * SA_BYTES)                  // 81920

// ---------------- device scratch ----------------
__device__ __align__(16) float g_xh[SEQ * BATCH * HID];               // xh + biases; phase-A reds land here
__device__ __align__(16) float g_h[BATCH * HID];
__device__ __align__(16) __half g_hallf[SEQ * BATCH * KF1];           // 16.8 MB
__device__ __align__(16) __half g_wfcf[OUT_DIM * HID];                // 64 MB
__device__ __align__(16) __half g_wihf[HID * HID];                    // 2 MB
__device__ __align__(16) __half g_embf[SEQ * BATCH * KE];             // 33.5 MB [hi|lo]
__device__ __align__(16) __nv_bfloat16 g_whh2[HID * K2H];             // 4 MB [hi|lo] chunked
__device__ __align__(16) __nv_bfloat16 g_h2[BATCH * K2H];             // 256KB [hi|lo] chunked
__device__ int g_is64;
__device__ unsigned g_arrive;

// ---------------- helpers ----------------
__device__ __forceinline__ uint32_t smem_u32(const void* p) {
    uint32_t a;
    asm("{ .reg .u64 t; cvta.to.shared.u64 t, %1; cvt.u32.u64 %0, t; }" : "=r"(a) : "l"(p));
    return a;
}
__device__ __forceinline__ void cp16(uint32_t s, const void* g) {
    asm volatile("cp.async.cg.shared.global [%0], [%1], 16;" :: "r"(s), "l"(g) : "memory");
}
__device__ __forceinline__ void ldmx4(uint32_t& r0, uint32_t& r1, uint32_t& r2, uint32_t& r3, uint32_t addr) {
    asm volatile("ldmatrix.sync.aligned.m8n8.x4.shared.b16 {%0,%1,%2,%3}, [%4];"
                 : "=r"(r0), "=r"(r1), "=r"(r2), "=r"(r3) : "r"(addr));
}
__device__ __forceinline__ void mma_bf16(float* c, const uint32_t* a, const uint32_t* b) {
    asm volatile("mma.sync.aligned.m16n8k16.row.col.f32.bf16.bf16.f32 "
                 "{%0,%1,%2,%3}, {%4,%5,%6,%7}, {%8,%9}, {%0,%1,%2,%3};"
                 : "+f"(c[0]), "+f"(c[1]), "+f"(c[2]), "+f"(c[3])
                 : "r"(a[0]), "r"(a[1]), "r"(a[2]), "r"(a[3]), "r"(b[0]), "r"(b[1]));
}
__device__ __forceinline__ void mma_fp16(float* c, const uint32_t* a, const uint32_t* b) {
    asm volatile("mma.sync.aligned.m16n8k16.row.col.f32.f16.f16.f32 "
                 "{%0,%1,%2,%3}, {%4,%5,%6,%7}, {%8,%9}, {%0,%1,%2,%3};"
                 : "+f"(c[0]), "+f"(c[1]), "+f"(c[2]), "+f"(c[3])
                 : "r"(a[0]), "r"(a[1]), "r"(a[2]), "r"(a[3]), "r"(b[0]), "r"(b[1]));
}
// grid sync: release/acquire monotonic counter
__device__ __forceinline__ void gsync(unsigned target) {
    __syncthreads();
    if (threadIdx.x == 0) {
        asm volatile("red.release.gpu.global.add.u32 [%0], 1;" :: "l"(&g_arrive) : "memory");
        unsigned v;
        do {
            asm volatile("ld.acquire.gpu.global.u32 %0, [%1];" : "=r"(v) : "l"(&g_arrive) : "memory");
        } while (v < target);
    }
    __syncthreads();
}

// ---------------- small kernels ----------------
// dtype sniff only (single block)
__global__ void k_prep(const void* x) {
    __shared__ int bad;
    if (threadIdx.x == 0) bad = 0;
    __syncthreads();
    const unsigned long long* p = (const unsigned long long*)x;
    int mybad = 0;
    for (int i = threadIdx.x; i < 4096; i += 256)
        if (p[i] >= (unsigned long long)VOCAB) mybad = 1;
    if (mybad) atomicOr(&bad, 1);
    __syncthreads();
    if (threadIdx.x == 0) g_is64 = bad ? 0 : 1;
}
// init h (fp32) + h2 ([hi|lo] chunked) and reset grid-sync counter
__global__ void k_copyh(const float* __restrict__ hidden) {
    int i = blockIdx.x * 256 + threadIdx.x;
    if (i == 0) g_arrive = 0;
    if (i >= BATCH * HID) return;
    float v = hidden[i];
    g_h[i] = v;
    __nv_bfloat16 hi = __float2bfloat16(v);
    __nv_bfloat16 lo = __float2bfloat16(v - __bfloat162float(hi));
    int b = i >> 10, j = i & 1023;
    int c = j >> 7, o = j & 127;
    __nv_bfloat16* hb = g_h2 + (size_t)b * K2H + c * 256 + o;
    hb[0] = hi; hb[128] = lo;
}
// W_hh fp32 -> bf16 chunked [hi | lo] per 128-k chunk
__global__ void k_conv_whh(const float* __restrict__ W) {
    int i = blockIdx.x * 256 + threadIdx.x;
    if (i >= HID * HID) return;
    float v = W[i];
    __nv_bfloat16 hi = __float2bfloat16(v);
    __nv_bfloat16 lo = __float2bfloat16(v - __bfloat162float(hi));
    int row = i >> 10, j = i & 1023;
    int c = j >> 7, o = j & 127;
    __nv_bfloat16* b = g_whh2 + (size_t)row * K2H + c * 256 + o;
    b[0] = hi; b[128] = lo;
}
// fp32 -> fp16 (vectorized), for W_fc and W_ih
__global__ void k_convw_f(const float* __restrict__ W, __half* __restrict__ dst, int n4) {
    int i = blockIdx.x * 256 + threadIdx.x;
    if (i >= n4) return;
    float4 v = ((const float4*)W)[i];
    __half2 a = __floats2half2_rn(v.x, v.y);
    __half2 b = __floats2half2_rn(v.z, v.w);
    ((uint2*)dst)[i] = make_uint2(*(uint32_t*)&a, *(uint32_t*)&b);
}
// gather emb rows (reads x directly per g_is64), split to fp16 segments [hi | lo]
__global__ void k_gather_split(const float* __restrict__ emb, const void* __restrict__ x) {
    int r = blockIdx.x;
    int t = threadIdx.x;
    long long src = g_is64 ? (long long)((const long long*)x)[r]
                           : (long long)((const int*)x)[r];
    float4 v = ((const float4*)(emb + (size_t)src * 1024))[t];
    __half h0 = __float2half(v.x), h1 = __float2half(v.y);
    __half h2 = __float2half(v.z), h3 = __float2half(v.w);
    __half l0 = __float2half(v.x - __half2float(h0));
    __half l1 = __float2half(v.y - __half2float(h1));
    __half l2 = __float2half(v.z - __half2float(h2));
    __half l3 = __float2half(v.w - __half2float(h3));
    uint2 hp, lp;
    ((__half*)&hp)[0] = h0; ((__half*)&hp)[1] = h1;
    ((__half*)&hp)[2] = h2; ((__half*)&hp)[3] = h3;
    ((__half*)&lp)[0] = l0; ((__half*)&lp)[1] = l1;
    ((__half*)&lp)[2] = l2; ((__half*)&lp)[3] = l3;
    __half* base = g_embf + (size_t)r * KE;
    ((uint2*)base)[t] = hp;
    ((uint2*)(base + 1024))[t] = lp;
}

// ---------------- persistent recurrence (HMMA bf16 3-term, dedup operands) ----------------
// 128 blocks (16 nx x 8 kz) x 256 thr. W slice [hi|lo] SMEM-resident per chunk
// (40960B); h slice [hi|lo] loaded per step (40960B). 3 term-products per
// subchunk reuse hi fragments. Phase A: 64x64 partial -> float2 atomicAdd into
// g_xh[s]. Phase B: tanh + emits.
__global__ void __launch_bounds__(256) k_rnn_persist(float* __restrict__ out,
                                                     int s_begin, int s_end,
                                                     unsigned tbase, int writeTail) {
    extern __shared__ __align__(16) char smem[];
    const uint32_t sA = smem_u32(smem);
    const uint32_t sB = sA + SA_BYTES;
    const int t = threadIdx.x;
    const int lane = t & 31, wid = t >> 5;
    const int warp_m = wid & 1;
    const int warp_n = wid >> 1;
    const int bid = blockIdx.x;
    const int nx = bid & 15, kz = bid >> 4;
    const int n0 = nx * 64;
    const int r = t >> 2, q = t & 3;

    const char* hsrc = (const char*)g_h2 + (size_t)r * (K2H * 2) + kz * 512 + q * 16;
    const char* wsrc = (const char*)g_whh2 + (size_t)(n0 + r) * (K2H * 2) + kz * 512 + q * 16;
    const uint32_t sAoff = sA + r * SROW + q * 16;
    const uint32_t sBoff = sB + r * SROW + q * 16;

    const int arow = ((lane >> 3) & 1) * 8 + (lane & 7);
    const int ahalf = (lane >> 4) & 1;
    const int brow = ((lane >> 4) & 1) * 8 + (lane & 7);
    const int bhalf = (lane >> 3) & 1;

    const int i0 = bid * 512 + t;

    // W slice ([hi|lo], 8 subchunks) -> SMEM once per chunk launch
#pragma unroll
    for (int i = 0; i < SUBL; i++) cp16(sBoff + i * (64 * SROW), wsrc + i * 64);
    asm volatile("cp.async.commit_group;" ::: "memory");
    asm volatile("cp.async.wait_group 0;" ::: "memory");
    __syncthreads();

    unsigned target = tbase;
    for (int s = s_begin; s < s_end; s++) {
        float* xs = g_xh + (size_t)s * (BATCH * HID);

        // phase A: load h slice ([hi|lo], 8 subchunks), 3-term mma, red into xs
#pragma unroll
        for (int i = 0; i < SUBL; i++) cp16(sAoff + i * (64 * SROW), hsrc + i * 64);
        asm volatile("cp.async.commit_group;" ::: "memory");
        asm volatile("cp.async.wait_group 0;" ::: "memory");
        __syncthreads();

        float acc[2][2][4];
#pragma unroll
        for (int mt = 0; mt < 2; mt++)
#pragma unroll
            for (int nt = 0; nt < 2; nt++)
#pragma unroll
                for (int e = 0; e < 4; e++) acc[mt][nt][e] = 0.f;

#pragma unroll
        for (int sub = 0; sub < 4; sub++) {
#pragma unroll
            for (int kp = 0; kp < 2; kp++) {
                uint32_t ah[2][4], al[2][4], bh[4], bl[4];
#pragma unroll
                for (int mt = 0; mt < 2; mt++) {
                    uint32_t abase = (warp_m * 32 + mt * 16 + arow) * SROW + ahalf * 16 + kp * 32;
                    ldmx4(ah[mt][0], ah[mt][1], ah[mt][2], ah[mt][3],
                          sA + sub * (64 * SROW) + abase);
                    ldmx4(al[mt][0], al[mt][1], al[mt][2], al[mt][3],
                          sA + (4 + sub) * (64 * SROW) + abase);
                }
                uint32_t bbase = (warp_n * 16 + brow) * SROW + bhalf * 16 + kp * 32;
                ldmx4(bh[0], bh[1], bh[2], bh[3], sB + sub * (64 * SROW) + bbase);
                ldmx4(bl[0], bl[1], bl[2], bl[3], sB + (4 + sub) * (64 * SROW) + bbase);
                // hi*hi + hi*lo + lo*hi
#pragma unroll
                for (int mt = 0; mt < 2; mt++) {
                    mma_bf16(acc[mt][0], ah[mt], &bh[0]);
                    mma_bf16(acc[mt][1], ah[mt], &bh[2]);
                    mma_bf16(acc[mt][0], ah[mt], &bl[0]);
                    mma_bf16(acc[mt][1], ah[mt], &bl[2]);
                    mma_bf16(acc[mt][0], al[mt], &bh[0]);
                    mma_bf16(acc[mt][1], al[mt], &bh[2]);
                }
            }
        }
#pragma unroll
        for (int mt = 0; mt < 2; mt++) {
            int row = warp_m * 32 + mt * 16 + (lane >> 2);
#pragma unroll
            for (int nt = 0; nt < 2; nt++) {
                int col = n0 + warp_n * 16 + nt * 8 + (lane & 3) * 2;
                atomicAdd((float2*)&xs[(size_t)row * 1024 + col],
                          make_float2(acc[mt][nt][0], acc[mt][nt][1]));
                atomicAdd((float2*)&xs[(size_t)(row + 8) * 1024 + col],
                          make_float2(acc[mt][nt][2], acc[mt][nt][3]));
            }
        }

        target += RNN_BLOCKS;
        gsync(target);

        // phase B: tanh + emits
#pragma unroll
        for (int e = 0; e < 2; e++) {
            int i = i0 + e * 256;
            float h = tanhf(__ldcg(&xs[i]));
            int b = i >> 10, j = i & 1023;
            g_hallf[(size_t)(s * BATCH + b) * KF1 + j] = __float2half(h);
            __nv_bfloat16 hi = __float2bfloat16(h);
            __nv_bfloat16 lo = __float2bfloat16(h - __bfloat162float(hi));
            int c = j >> 7, o = j & 127;
            __nv_bfloat16* hb = g_h2 + (size_t)b * K2H + c * 256 + o;
            hb[0] = hi; hb[128] = lo;
            if (s == SEQ - 1) __stcg(&g_h[i], h);
        }

        target += RNN_BLOCKS;
        gsync(target);
    }

    // final hidden -> out tail (last chunk only)
    if (writeTail) {
#pragma unroll
        for (int e = 0; e < 2; e++) {
            int i = i0 + e * 256;
            out[(size_t)SEQ * BATCH * OUT_DIM + i] = __ldcg(&g_h[i]);
        }
    }
}

// ---------------- HMMA GEMM: C[M,N] = A @ B^T + bias ----------------
// 128x128 block, 4 warps (2x2) of 64x64. m-fastest. B k-chunk wraps by bkmask.
template<bool FP16>
__global__ void __launch_bounds__(128, 2)
gemm_tc(const char* __restrict__ A2, const char* __restrict__ B2,
        float* __restrict__ C, const float* __restrict__ bias0,
        const float* __restrict__ bias1, int mblocks, int ldc, int nbias,
        int kaElems, int kbElems, int nkt, int bkmask)
{
    extern __shared__ __align__(16) char smem[];
    const uint32_t sBase = smem_u32(smem);
    const int t = threadIdx.x;
    const int lane = t & 31, wid = t >> 5;
    const int warp_m = wid & 1;
    const int warp_n = wid >> 1;

    const int m0 = (blockIdx.x % mblocks) * BM;
    const int n0 = (blockIdx.x / mblocks) * BN;

    uint32_t soffA[4], soffB[4];
    const char *gA[4], *gB[4];
#pragma unroll
    for (int i = 0; i < 4; i++) {
        int c = t + 128 * i;
        int row = c >> 2, q = c & 3;
        soffA[i] = (uint32_t)(row * SROW + q * 16);
        soffB[i] = (uint32_t)(BM * SROW + row * SROW + q * 16);
        gA[i] = A2 + ((size_t)(m0 + row) * kaElems + q * 8) * 2;
        gB[i] = B2 + ((size_t)(n0 + row) * kbElems + q * 8) * 2;
    }

    const int arow = ((lane >> 3) & 1) * 8 + (lane & 7);
    const int ahalf = (lane >> 4) & 1;
    const uint32_t aOff = (uint32_t)((warp_m * 64 + arow) * SROW + ahalf * 16);
    const int brow = ((lane >> 4) & 1) * 8 + (lane & 7);
    const int bhalf = (lane >> 3) & 1;
    const uint32_t bOff = (uint32_t)(BM * SROW + (warp_n * 64 + brow) * SROW + bhalf * 16);

    float acc[4][8][4];
#pragma unroll
    for (int mt = 0; mt < 4; mt++)
#pragma unroll
        for (int nt = 0; nt < 8; nt++)
#pragma unroll
            for (int e = 0; e < 4; e++) acc[mt][nt][e] = 0.f;

#pragma unroll
    for (int p = 0; p < STAGES_TC - 1; p++) {
        uint32_t stg = sBase + p * STG_BYTES_TC;
        size_t ka = (size_t)p * 64;
        size_t kb = (size_t)(p & bkmask) * 64;
#pragma unroll
        for (int i = 0; i < 4; i++) cp16(stg + soffA[i], gA[i] + ka);
#pragma unroll
        for (int i = 0; i < 4; i++) cp16(stg + soffB[i], gB[i] + kb);
        asm volatile("cp.async.commit_group;" ::: "memory");
    }

    for (int kt = 0; kt < nkt; kt++) {
        if (kt < nkt - 2)       asm volatile("cp.async.wait_group 2;" ::: "memory");
        else if (kt == nkt - 2) asm volatile("cp.async.wait_group 1;" ::: "memory");
        else                    asm volatile("cp.async.wait_group 0;" ::: "memory");
        __syncthreads();

        if (kt + 3 < nkt) {
            uint32_t stg2 = sBase + ((kt + 3) & 3) * STG_BYTES_TC;
            size_t ka = (size_t)(kt + 3) * 64;
            size_t kb = (size_t)((kt + 3) & bkmask) * 64;
#pragma unroll
            for (int i = 0; i < 4; i++) cp16(stg2 + soffA[i], gA[i] + ka);
#pragma unroll
            for (int i = 0; i < 4; i++) cp16(stg2 + soffB[i], gB[i] + kb);
            asm volatile("cp.async.commit_group;" ::: "memory");
        }

        const uint32_t stg = sBase + (kt & 3) * STG_BYTES_TC;
#pragma unroll
        for (int kp = 0; kp < 2; kp++) {
            uint32_t af[4][4], bf[4][4];
#pragma unroll
            for (int mt = 0; mt < 4; mt++)
                ldmx4(af[mt][0], af[mt][1], af[mt][2], af[mt][3],
                      stg + aOff + mt * 16 * SROW + kp * 32);
#pragma unroll
            for (int p = 0; p < 4; p++)
                ldmx4(bf[p][0], bf[p][1], bf[p][2], bf[p][3],
                      stg + bOff + p * 16 * SROW + kp * 32);
#pragma unroll
            for (int mt = 0; mt < 4; mt++)
#pragma unroll
                for (int nt = 0; nt < 8; nt++) {
                    if (FP16) mma_fp16(acc[mt][nt], af[mt], &bf[nt >> 1][(nt & 1) * 2]);
                    else      mma_bf16(acc[mt][nt], af[mt], &bf[nt >> 1][(nt & 1) * 2]);
                }
        }
    }

#pragma unroll
    for (int mt = 0; mt < 4; mt++) {
        int row = m0 + warp_m * 64 + mt * 16 + (lane >> 2);
#pragma unroll
        for (int nt = 0; nt < 8; nt++) {
            int col = n0 + warp_n * 64 + nt * 8 + (lane & 3) * 2;
            float b0 = 0.f, b1 = 0.f;
            if (nbias >= 1) { b0 += __ldg(&bias0[col]); b1 += __ldg(&bias0[col + 1]); }
            if (nbias >= 2) { b0 += __ldg(&bias1[col]); b1 += __ldg(&bias1[col + 1]); }
            float2 v0 = make_float2(acc[mt][nt][0] + b0, acc[mt][nt][1] + b1);
            float2 v1 = make_float2(acc[mt][nt][2] + b0, acc[mt][nt][3] + b1);
            *(float2*)&C[(size_t)row * ldc + col] = v0;
            *(float2*)&C[(size_t)(row + 8) * ldc + col] = v1;
        }
    }
}

// ---------------- launch ----------------
extern "C" void kernel_launch(void* const* d_in, const int* in_sizes, int n_in,
                              void* d_out, int out_size)
{
    const void*  x      = d_in[0];
    const float* hidden = (const float*)d_in[1];
    const float* emb    = (const float*)d_in[2];
    const float* W_ih   = (const float*)d_in[3];
    const float* W_hh   = (const float*)d_in[4];
    const float* b_ih   = (const float*)d_in[5];
    const float* b_hh   = (const float*)d_in[6];
    const float* W_fc   = (const float*)d_in[7];
    const float* b_fc   = (const float*)d_in[8];
    float* out = (float*)d_out;

    float* p_xh;
    void *p_hallf, *p_wfcf, *p_wihf, *p_embf;
    cudaGetSymbolAddress((void**)&p_xh, g_xh);
    cudaGetSymbolAddress(&p_hallf, g_hallf);
    cudaGetSymbolAddress(&p_wfcf,  g_wfcf);
    cudaGetSymbolAddress(&p_wihf,  g_wihf);
    cudaGetSymbolAddress(&p_embf,  g_embf);

    cudaFuncSetAttribute(gemm_tc<true>,  cudaFuncAttributeMaxDynamicSharedMemorySize, SMEM_TC);
    cudaFuncSetAttribute(gemm_tc<false>, cudaFuncAttributeMaxDynamicSharedMemorySize, SMEM_TC);
    cudaFuncSetAttribute(k_rnn_persist,  cudaFuncAttributeMaxDynamicSharedMemorySize, SMEM_RNN);

    // side stream: W_fc convert + rec-prep converts, joined where needed.
    cudaStream_t gs;
    cudaStreamCreateWithFlags(&gs, cudaStreamNonBlocking);
    cudaEvent_t evRoot, evW, evJoin, evF[NCH];
    cudaEventCreateWithFlags(&evRoot, cudaEventDisableTiming);
    cudaEventCreateWithFlags(&evW,    cudaEventDisableTiming);
    cudaEventCreateWithFlags(&evJoin, cudaEventDisableTiming);
    for (int c = 0; c < NCH; c++) cudaEventCreateWithFlags(&evF[c], cudaEventDisableTiming);

    // fork side stream; W_fc convert + rec-only preps run there under the xh path
    cudaEventRecord(evRoot, 0);
    cudaStreamWaitEvent(gs, evRoot, 0);
    k_convw_f<<<(OUT_DIM * HID / 4 + 255) / 256, 256, 0, gs>>>(W_fc, (__half*)p_wfcf, OUT_DIM * HID / 4);
    k_conv_whh<<<(HID * HID) / 256, 256, 0, gs>>>(W_hh);
    k_copyh<<<(BATCH * HID + 255) / 256, 256, 0, gs>>>(hidden);
    cudaEventRecord(evW, gs);

    // main stream: sniff + gather + W_ih convert + xh GEMM
    k_prep<<<1, 256>>>(x);
    k_gather_split<<<SEQ * BATCH, 256>>>(emb, x);
    k_convw_f<<<(HID * HID / 4 + 255) / 256, 256>>>(W_ih, (__half*)p_wihf, HID * HID / 4);

    // xh = embf @ wihf^T + b_ih + b_hh : fp16 2-term (B wraps), M=8192, N=1024
    gemm_tc<true><<<64 * (HID / BN), 128, SMEM_TC>>>(
        (const char*)p_embf, (const char*)p_wihf, p_xh, b_ih, b_hh,
        64, HID, 2, KE, HID, KE / BKK, 31);

    // rec needs whh2/h2/counter from gs
    cudaStreamWaitEvent(0, evW, 0);

    // recurrence chunks on main; per-chunk output GEMM forked onto gs
    for (int c = 0; c < NCH; c++) {
        int s0 = c * CH_STEPS;
        k_rnn_persist<<<RNN_BLOCKS, 256, SMEM_RNN>>>(
            out, s0, s0 + CH_STEPS, (unsigned)(2 * s0 * RNN_BLOCKS), c == NCH - 1);
        cudaEventRecord(evF[c], 0);
        cudaStreamWaitEvent(gs, evF[c], 0);
        gemm_tc<true><<<(CH_ROWS / BM) * (OUT_DIM / BN), 128, SMEM_TC, gs>>>(
            (const char*)p_hallf + (size_t)c * CH_ROWS * KF1 * 2,
            (const char*)p_wfcf,
            out + (size_t)c * CH_ROWS * OUT_DIM,
            b_fc, nullptr,
            CH_ROWS / BM, OUT_DIM, 1, KF1, HID, KF1 / BKK, 0xFF);
    }

    // join side stream back into the capture/origin stream
    cudaEventRecord(evJoin, gs);
    cudaStreamWaitEvent(0, evJoin, 0);
}